// round 14
// baseline (speedup 1.0000x reference)
#include <cuda_runtime.h>
#include <cuda_bf16.h>
#include <cstdint>

// ---------------- problem constants ----------------
static constexpr int NROWS   = 8192;
static constexpr int DDIM    = 1024;              // elements = bytes per int8 row
static constexpr float MARGIN = 0.3f;

static constexpr float QSCALE   = 28.0f;          // x -> round(x*28), clip +-127 (4.54 sigma)
static constexpr float INV_QSQ  = 1.0f / (QSCALE * QSCALE);

// CTA tile: 128 (M, A-rows) x 256 (N, B-rows)
static constexpr int BM = 128;
static constexpr int BN = 256;
// triangular cover: row-tile bi (of 64) needs col-tiles 0..bi/2 -> 1056 blocks
static constexpr int NBLOCKS = 1056;

static constexpr int STAGES      = 3;
static constexpr int CHUNK       = 128;               // int8 k-elems per stage (128 B/row)
static constexpr int NKCHUNKS    = DDIM / CHUNK;      // 8
static constexpr int A_BYTES     = BM * 128;          // 16 KB
static constexpr int B_BYTES     = BN * 128;          // 32 KB
static constexpr int STAGE_BYTES = A_BYTES + B_BYTES; // 48 KB
static constexpr int SMEM_TOTAL  = STAGES * STAGE_BYTES; // 144 KB dynamic

static constexpr int NTHREADS = 512;                  // 16 warps -> 4 per SMSP

// ---------------- scratch (no allocs allowed) ----------------
__device__ int8_t g_x8[(size_t)NROWS * DDIM];   // 8MB int8 copy of X
__device__ int   g_tgt[NROWS];
__device__ float g_partials[NBLOCKS];

// ---------------- helpers ----------------
__device__ __forceinline__ uint32_t smem_to_u32(const void* p) {
    uint32_t a;
    asm("{ .reg .u64 t; cvta.to.shared.u64 t, %1; cvt.u32.u64 %0, t; }" : "=r"(a) : "l"(p));
    return a;
}
#define SW128(off) ((off) ^ (((off) >> 3) & 0x70))

__device__ __forceinline__ void cp_async16(uint32_t smem_dst, const void* gptr) {
    asm volatile("cp.async.cg.shared.global [%0], [%1], 16;"
        :: "r"(smem_dst), "l"(__cvta_generic_to_global(gptr)) : "memory");
}
__device__ __forceinline__ void cp_commit() {
    asm volatile("cp.async.commit_group;" ::: "memory");
}
template <int N> __device__ __forceinline__ void cp_wait() {
    asm volatile("cp.async.wait_group %0;" :: "n"(N) : "memory");
}

__device__ __forceinline__ void ldmatrix_x4(uint32_t& r0, uint32_t& r1, uint32_t& r2, uint32_t& r3,
                                            uint32_t addr) {
    asm volatile("ldmatrix.sync.aligned.m8n8.x4.shared.b16 {%0,%1,%2,%3}, [%4];"
        : "=r"(r0), "=r"(r1), "=r"(r2), "=r"(r3) : "r"(addr));
}

// D(s32) += A(16x32 s8 row) * B(32x8 s8 col); fragment byte-layout identical to bf16 16816
__device__ __forceinline__ void mma_s8(int* c, const uint32_t* a, uint32_t b0, uint32_t b1) {
    asm volatile("mma.sync.aligned.m16n8k32.row.col.s32.s8.s8.s32 "
        "{%0,%1,%2,%3}, {%4,%5,%6,%7}, {%8,%9}, {%0,%1,%2,%3};"
        : "+r"(c[0]), "+r"(c[1]), "+r"(c[2]), "+r"(c[3])
        : "r"(a[0]), "r"(a[1]), "r"(a[2]), "r"(a[3]), "r"(b0), "r"(b1));
}

// ---------------- kernel 1: fp32 -> int8 + targets ----------------
__global__ void convert_kernel(const float* __restrict__ x, const int* __restrict__ tgt) {
    int tid = blockIdx.x * blockDim.x + threadIdx.x;
    int nthreads = gridDim.x * blockDim.x;
    const float4* x4 = (const float4*)x;
    uint32_t* out = (uint32_t*)g_x8;
    const int n4 = NROWS * DDIM / 4;
    for (int i = tid; i < n4; i += nthreads) {
        float4 v = x4[i];
        int q0 = max(-127, min(127, __float2int_rn(v.x * QSCALE)));
        int q1 = max(-127, min(127, __float2int_rn(v.y * QSCALE)));
        int q2 = max(-127, min(127, __float2int_rn(v.z * QSCALE)));
        int q3 = max(-127, min(127, __float2int_rn(v.w * QSCALE)));
        out[i] = (uint32_t)(uint8_t)q0 | ((uint32_t)(uint8_t)q1 << 8)
               | ((uint32_t)(uint8_t)q2 << 16) | ((uint32_t)(uint8_t)q3 << 24);
    }
    if (tid < NROWS) g_tgt[tid] = tgt[tid];
}

// ---------------- kernel 2: 128x256-tile int8 GEMM + fused epilogue --------
__global__ void __launch_bounds__(NTHREADS, 1)
gemm_loss_kernel() {
    extern __shared__ char smem[];
    __shared__ int   s_tgtA[BM];
    __shared__ int   s_tgtB[BN];
    __shared__ float s_red[16];

    const uint32_t smem_base = smem_to_u32(smem);
    const int tid = threadIdx.x;
    const int wid = tid >> 5;
    const int lid = tid & 31;

    // block -> (bi, bjc): row-tile bi has (bi/2 + 1) col-tiles
    int k = blockIdx.x;
    int bi = 0;
    for (;;) {
        int nb = (bi >> 1) + 1;
        if (k < nb) break;
        k -= nb;
        bi++;
    }
    const int bjc = k;
    const int row0 = bi * BM;
    const int col0 = bjc * BN;

    if (tid < BM) s_tgtA[tid] = g_tgt[row0 + tid];
    if (tid < BN) s_tgtB[tid] = g_tgt[col0 + tid];

    // warp layout: 2 warps along M (64 rows), 8 along N (32 cols); warp tile 64x32
    const int warp_m = (wid & 1) * 64;
    const int warp_n = (wid >> 1) * 32;

    // ---- cp.async fill assignments (512 threads), 128B per row per chunk ----
    // A: thread t -> row t>>2 (0..127), quarter (t&3)*32: 2 x 16B
    // B: thread t -> row t>>1 (0..255), half (t&1)*64:    4 x 16B
    const int arow = tid >> 2;
    const int aq   = (tid & 3) * 32;
    const int brow = tid >> 1;
    const int bh   = (tid & 1) * 64;
    const char* gArow = (const char*)g_x8 + ((size_t)(row0 + arow)) * DDIM + aq;
    const char* gBrow = (const char*)g_x8 + ((size_t)(col0 + brow)) * DDIM + bh;

    auto fill = [&](int kc, int buf) {
        uint32_t sA = smem_base + buf * STAGE_BYTES;
        uint32_t sB = sA + A_BYTES;
        const char* ga = gArow + kc * CHUNK;
        const char* gb = gBrow + kc * CHUNK;
        #pragma unroll
        for (int j = 0; j < 2; j++) {
            uint32_t off = SW128((uint32_t)(arow * 128 + aq + j * 16));
            cp_async16(sA + off, ga + j * 16);
        }
        #pragma unroll
        for (int j = 0; j < 4; j++) {
            uint32_t off = SW128((uint32_t)(brow * 128 + bh + j * 16));
            cp_async16(sB + off, gb + j * 16);
        }
    };

    // ---- accumulators: warp tile 64x32 = 4 (m16) x 4 (n8) s32 fragments ----
    int c[4][4][4];
    #pragma unroll
    for (int mi = 0; mi < 4; mi++)
        #pragma unroll
        for (int ni = 0; ni < 4; ni++)
            #pragma unroll
            for (int e = 0; e < 4; e++) c[mi][ni][e] = 0;

    const int lrow  = lid & 15;           // row within 16-row ldmatrix group
    const int lkoff = (lid >> 4) * 16;    // 0 or 16 bytes (k half of 32B step)

    // prologue
    #pragma unroll
    for (int s = 0; s < STAGES - 1; s++) { fill(s, s); cp_commit(); }

    for (int kc = 0; kc < NKCHUNKS; kc++) {
        const int buf = kc % STAGES;
        cp_wait<STAGES - 2>();
        __syncthreads();

        const int kf = kc + STAGES - 1;
        if (kf < NKCHUNKS) fill(kf, kf % STAGES);
        cp_commit();

        const uint32_t sA = smem_base + buf * STAGE_BYTES;
        const uint32_t sB = sA + A_BYTES;

        #pragma unroll
        for (int ks = 0; ks < 4; ks++) {   // 4 k-steps of 32 bytes (=32 int8 k-elems)
            const int kbyte = ks * 32 + lkoff;
            uint32_t a[4][4];
            #pragma unroll
            for (int mi = 0; mi < 4; mi++) {
                uint32_t off = SW128((uint32_t)((warp_m + mi * 16 + lrow) * 128 + kbyte));
                ldmatrix_x4(a[mi][0], a[mi][1], a[mi][2], a[mi][3], sA + off);
            }
            uint32_t b[2][4];
            #pragma unroll
            for (int ng = 0; ng < 2; ng++) {
                uint32_t off = SW128((uint32_t)((warp_n + ng * 16 + lrow) * 128 + kbyte));
                ldmatrix_x4(b[ng][0], b[ng][1], b[ng][2], b[ng][3], sB + off);
            }
            #pragma unroll
            for (int mi = 0; mi < 4; mi++)
                #pragma unroll
                for (int ni = 0; ni < 4; ni++) {
                    const int ng = ni >> 1, s2 = ni & 1;
                    mma_s8(c[mi][ni], a[mi], b[ng][s2], b[ng][2 + s2]);
                }
        }
    }
    __syncthreads();

    // ---- fused epilogue: dequant + masked hinge sums, strict lower triangle (w=2) ----
    float acc = 0.0f;
    #pragma unroll
    for (int mi = 0; mi < 4; mi++) {
        const int lr0 = warp_m + mi * 16 + (lid >> 2);
        const int gr0 = row0 + lr0;
        const int gr1 = gr0 + 8;
        const int tr0 = s_tgtA[lr0];
        const int tr1 = s_tgtA[lr0 + 8];
        #pragma unroll
        for (int ni = 0; ni < 4; ni++) {
            const int lc0 = warp_n + ni * 8 + 2 * (lid & 3);
            const int gc0 = col0 + lc0;
            const int gc1 = gc0 + 1;
            const int tc0 = s_tgtB[lc0];
            const int tc1 = s_tgtB[lc0 + 1];
            const float f0 = (float)c[mi][ni][0] * INV_QSQ;
            const float f1 = (float)c[mi][ni][1] * INV_QSQ;
            const float f2 = (float)c[mi][ni][2] * INV_QSQ;
            const float f3 = (float)c[mi][ni][3] * INV_QSQ;
            if (gc0 < gr0) {
                if (tr0 == tc0) { if (f0 < 1.0f) acc += 1.0f - f0; } else if (f0 > MARGIN) acc += f0;
            }
            if (gc1 < gr0) {
                if (tr0 == tc1) { if (f1 < 1.0f) acc += 1.0f - f1; } else if (f1 > MARGIN) acc += f1;
            }
            if (gc0 < gr1) {
                if (tr1 == tc0) { if (f2 < 1.0f) acc += 1.0f - f2; } else if (f2 > MARGIN) acc += f2;
            }
            if (gc1 < gr1) {
                if (tr1 == tc1) { if (f3 < 1.0f) acc += 1.0f - f3; } else if (f3 > MARGIN) acc += f3;
            }
        }
    }
    #pragma unroll
    for (int o = 16; o; o >>= 1) acc += __shfl_xor_sync(0xFFFFFFFFu, acc, o);
    if (lid == 0) s_red[wid] = acc;
    __syncthreads();
    if (tid == 0) {
        float tot = 0.0f;
        #pragma unroll
        for (int w = 0; w < 16; w++) tot += s_red[w];
        g_partials[blockIdx.x] = 2.0f * tot;
    }
}

// ---------------- kernel 3: deterministic final reduction ----------------
__global__ void reduce_kernel(float* __restrict__ out) {
    __shared__ float s[256];
    float v = 0.0f;
    for (int i = threadIdx.x; i < NBLOCKS; i += 256) v += g_partials[i];
    s[threadIdx.x] = v;
    __syncthreads();
    for (int o = 128; o; o >>= 1) {
        if (threadIdx.x < o) s[threadIdx.x] += s[threadIdx.x + o];
        __syncthreads();
    }
    if (threadIdx.x == 0) out[0] = s[0] / (float)NROWS;
}

// ---------------- launch ----------------
extern "C" void kernel_launch(void* const* d_in, const int* in_sizes, int n_in,
                              void* d_out, int out_size) {
    const float* x   = (const float*)d_in[0];
    const int*   tgt = (const int*)d_in[1];
    float* out = (float*)d_out;

    cudaFuncSetAttribute(gemm_loss_kernel, cudaFuncAttributeMaxDynamicSharedMemorySize, SMEM_TOTAL);

    convert_kernel<<<4096, 256>>>(x, tgt);
    gemm_loss_kernel<<<NBLOCKS, NTHREADS, SMEM_TOTAL>>>();
    reduce_kernel<<<1, 256>>>(out);
}

// round 15
// speedup vs baseline: 1.7827x; 1.7827x over previous
#include <cuda_runtime.h>
#include <cuda_fp16.h>
#include <cstdint>

// ---------------- problem constants ----------------
static constexpr int NROWS   = 8192;
static constexpr int DDIM    = 1024;
static constexpr float MARGIN = 0.3f;

// CTA tile: 128 (M, A-rows) x 256 (N, B-rows)
static constexpr int BM = 128;
static constexpr int BN = 256;
// triangular cover: row-tile bi (of 64) needs col-tiles 0..bi/2 -> 1056 blocks
static constexpr int NBLOCKS = 1056;

static constexpr int STAGES      = 3;
static constexpr int BK          = 64;                 // fp16 elems per K stage (128 B/row)
static constexpr int NKCHUNKS    = DDIM / BK;          // 16
static constexpr int A_BYTES     = BM * 128;           // 16 KB
static constexpr int B_BYTES     = BN * 128;           // 32 KB
static constexpr int STAGE_BYTES = A_BYTES + B_BYTES;  // 48 KB
static constexpr int SMEM_TOTAL  = STAGES * STAGE_BYTES; // 144 KB dynamic

static constexpr int NTHREADS = 512;                   // 16 warps -> 4 per SMSP

// ---------------- scratch (no allocs allowed) ----------------
__device__ __half g_xh[(size_t)NROWS * DDIM];   // 16MB fp16 copy of X
__device__ int   g_tgt[NROWS];
__device__ float g_partials[NBLOCKS];

// ---------------- helpers ----------------
__device__ __forceinline__ uint32_t smem_to_u32(const void* p) {
    uint32_t a;
    asm("{ .reg .u64 t; cvta.to.shared.u64 t, %1; cvt.u32.u64 %0, t; }" : "=r"(a) : "l"(p));
    return a;
}
#define SW128(off) ((off) ^ (((off) >> 3) & 0x70))

__device__ __forceinline__ void cp_async16(uint32_t smem_dst, const void* gptr) {
    asm volatile("cp.async.cg.shared.global [%0], [%1], 16;"
        :: "r"(smem_dst), "l"(__cvta_generic_to_global(gptr)) : "memory");
}
__device__ __forceinline__ void cp_commit() {
    asm volatile("cp.async.commit_group;" ::: "memory");
}
template <int N> __device__ __forceinline__ void cp_wait() {
    asm volatile("cp.async.wait_group %0;" :: "n"(N) : "memory");
}

__device__ __forceinline__ void ldmatrix_x4(uint32_t& r0, uint32_t& r1, uint32_t& r2, uint32_t& r3,
                                            uint32_t addr) {
    asm volatile("ldmatrix.sync.aligned.m8n8.x4.shared.b16 {%0,%1,%2,%3}, [%4];"
        : "=r"(r0), "=r"(r1), "=r"(r2), "=r"(r3) : "r"(addr));
}

// fp16 in, fp16 accumulate: D fragment = 2 x f16x2 regs
// c[0] = (row, col0|col1), c[1] = (row+8, col0|col1); row = lid>>2, col0 = 2*(lid&3)
__device__ __forceinline__ void mma_16816_f16(uint32_t* c, const uint32_t* a, uint32_t b0, uint32_t b1) {
    asm volatile("mma.sync.aligned.m16n8k16.row.col.f16.f16.f16.f16 "
        "{%0,%1}, {%2,%3,%4,%5}, {%6,%7}, {%0,%1};"
        : "+r"(c[0]), "+r"(c[1])
        : "r"(a[0]), "r"(a[1]), "r"(a[2]), "r"(a[3]), "r"(b0), "r"(b1));
}

// ---------------- kernel 1: fp32 -> fp16 + targets ----------------
__global__ void convert_kernel(const float* __restrict__ x, const int* __restrict__ tgt) {
    int tid = blockIdx.x * blockDim.x + threadIdx.x;
    int nthreads = gridDim.x * blockDim.x;
    const float4* x4 = (const float4*)x;
    uint2* out = (uint2*)g_xh;
    const int n4 = NROWS * DDIM / 4;
    for (int i = tid; i < n4; i += nthreads) {
        float4 v = x4[i];
        __half2 lo = __float22half2_rn(make_float2(v.x, v.y));
        __half2 hi = __float22half2_rn(make_float2(v.z, v.w));
        uint2 o;
        o.x = *(uint32_t*)&lo;
        o.y = *(uint32_t*)&hi;
        out[i] = o;
    }
    if (tid < NROWS) g_tgt[tid] = tgt[tid];
}

// ---------------- kernel 2: 128x256-tile fp16 GEMM + fused epilogue --------
__global__ void __launch_bounds__(NTHREADS, 1)
gemm_loss_kernel() {
    extern __shared__ char smem[];
    __shared__ int   s_tgtA[BM];
    __shared__ int   s_tgtB[BN];
    __shared__ float s_red[16];

    const uint32_t smem_base = smem_to_u32(smem);
    const int tid = threadIdx.x;
    const int wid = tid >> 5;
    const int lid = tid & 31;

    // block -> (bi, bjc): row-tile bi has (bi/2 + 1) col-tiles
    int k = blockIdx.x;
    int bi = 0;
    for (;;) {
        int nb = (bi >> 1) + 1;
        if (k < nb) break;
        k -= nb;
        bi++;
    }
    const int bjc = k;
    const int row0 = bi * BM;
    const int col0 = bjc * BN;

    if (tid < BM) s_tgtA[tid] = g_tgt[row0 + tid];
    if (tid < BN) s_tgtB[tid] = g_tgt[col0 + tid];

    // warp layout: 2 warps along M (64 rows), 8 along N (32 cols); warp tile 64x32
    const int warp_m = (wid & 1) * 64;
    const int warp_n = (wid >> 1) * 32;

    // ---- cp.async fill assignments (512 threads) ----
    // A: thread t -> row t>>2 (0..127), quarter (t&3)*32: 2 x 16B
    // B: thread t -> row t>>1 (0..255), half (t&1)*64:   4 x 16B
    const int arow = tid >> 2;
    const int aq   = (tid & 3) * 32;
    const int brow = tid >> 1;
    const int bh   = (tid & 1) * 64;
    const char* gArow = (const char*)g_xh + ((size_t)(row0 + arow)) * (DDIM * 2) + aq;
    const char* gBrow = (const char*)g_xh + ((size_t)(col0 + brow)) * (DDIM * 2) + bh;

    auto fill = [&](int kc, int buf) {
        uint32_t sA = smem_base + buf * STAGE_BYTES;
        uint32_t sB = sA + A_BYTES;
        const char* ga = gArow + kc * 128;
        const char* gb = gBrow + kc * 128;
        #pragma unroll
        for (int j = 0; j < 2; j++) {
            uint32_t off = SW128((uint32_t)(arow * 128 + aq + j * 16));
            cp_async16(sA + off, ga + j * 16);
        }
        #pragma unroll
        for (int j = 0; j < 4; j++) {
            uint32_t off = SW128((uint32_t)(brow * 128 + bh + j * 16));
            cp_async16(sB + off, gb + j * 16);
        }
    };

    // ---- accumulators: warp tile 64x32 = 4 (m16) x 4 (n8) f16x2-pair fragments ----
    uint32_t c[4][4][2];
    #pragma unroll
    for (int mi = 0; mi < 4; mi++)
        #pragma unroll
        for (int ni = 0; ni < 4; ni++) {
            c[mi][ni][0] = 0u;
            c[mi][ni][1] = 0u;
        }

    const int lrow  = lid & 15;           // row within 16-row ldmatrix group
    const int lkoff = (lid >> 4) * 16;    // 0 or 16 bytes (k half)

    // prologue
    #pragma unroll
    for (int s = 0; s < STAGES - 1; s++) { fill(s, s); cp_commit(); }

    for (int kc = 0; kc < NKCHUNKS; kc++) {
        const int buf = kc % STAGES;
        cp_wait<STAGES - 2>();
        __syncthreads();

        const int kf = kc + STAGES - 1;
        if (kf < NKCHUNKS) fill(kf, kf % STAGES);
        cp_commit();

        const uint32_t sA = smem_base + buf * STAGE_BYTES;
        const uint32_t sB = sA + A_BYTES;

        #pragma unroll
        for (int ks = 0; ks < BK / 16; ks++) {   // 4 k-steps of 16
            const int kbyte = ks * 32 + lkoff;
            uint32_t a[4][4];
            #pragma unroll
            for (int mi = 0; mi < 4; mi++) {
                uint32_t off = SW128((uint32_t)((warp_m + mi * 16 + lrow) * 128 + kbyte));
                ldmatrix_x4(a[mi][0], a[mi][1], a[mi][2], a[mi][3], sA + off);
            }
            uint32_t b[2][4];
            #pragma unroll
            for (int ng = 0; ng < 2; ng++) {
                uint32_t off = SW128((uint32_t)((warp_n + ng * 16 + lrow) * 128 + kbyte));
                ldmatrix_x4(b[ng][0], b[ng][1], b[ng][2], b[ng][3], sB + off);
            }
            #pragma unroll
            for (int mi = 0; mi < 4; mi++)
                #pragma unroll
                for (int ni = 0; ni < 4; ni++) {
                    const int ng = ni >> 1, s2 = ni & 1;
                    mma_16816_f16(c[mi][ni], a[mi], b[ng][s2], b[ng][2 + s2]);
                }
        }
    }
    __syncthreads();

    // ---- fused epilogue: unpack f16x2 + masked hinge sums, strict lower triangle (w=2) ----
    float acc = 0.0f;
    #pragma unroll
    for (int mi = 0; mi < 4; mi++) {
        const int lr0 = warp_m + mi * 16 + (lid >> 2);
        const int gr0 = row0 + lr0;
        const int gr1 = gr0 + 8;
        const int tr0 = s_tgtA[lr0];
        const int tr1 = s_tgtA[lr0 + 8];
        #pragma unroll
        for (int ni = 0; ni < 4; ni++) {
            const int lc0 = warp_n + ni * 8 + 2 * (lid & 3);
            const int gc0 = col0 + lc0;
            const int gc1 = gc0 + 1;
            const int tc0 = s_tgtB[lc0];
            const int tc1 = s_tgtB[lc0 + 1];
            float2 lo = __half22float2(*(const __half2*)&c[mi][ni][0]);  // (r0,c0),(r0,c1)
            float2 hi = __half22float2(*(const __half2*)&c[mi][ni][1]);  // (r1,c0),(r1,c1)
            const float f0 = lo.x, f1 = lo.y, f2 = hi.x, f3 = hi.y;
            if (gc0 < gr0) {
                if (tr0 == tc0) { if (f0 < 1.0f) acc += 1.0f - f0; } else if (f0 > MARGIN) acc += f0;
            }
            if (gc1 < gr0) {
                if (tr0 == tc1) { if (f1 < 1.0f) acc += 1.0f - f1; } else if (f1 > MARGIN) acc += f1;
            }
            if (gc0 < gr1) {
                if (tr1 == tc0) { if (f2 < 1.0f) acc += 1.0f - f2; } else if (f2 > MARGIN) acc += f2;
            }
            if (gc1 < gr1) {
                if (tr1 == tc1) { if (f3 < 1.0f) acc += 1.0f - f3; } else if (f3 > MARGIN) acc += f3;
            }
        }
    }
    #pragma unroll
    for (int o = 16; o; o >>= 1) acc += __shfl_xor_sync(0xFFFFFFFFu, acc, o);
    if (lid == 0) s_red[wid] = acc;
    __syncthreads();
    if (tid == 0) {
        float tot = 0.0f;
        #pragma unroll
        for (int w = 0; w < 16; w++) tot += s_red[w];
        g_partials[blockIdx.x] = 2.0f * tot;
    }
}

// ---------------- kernel 3: deterministic final reduction ----------------
__global__ void reduce_kernel(float* __restrict__ out) {
    __shared__ float s[256];
    float v = 0.0f;
    for (int i = threadIdx.x; i < NBLOCKS; i += 256) v += g_partials[i];
    s[threadIdx.x] = v;
    __syncthreads();
    for (int o = 128; o; o >>= 1) {
        if (threadIdx.x < o) s[threadIdx.x] += s[threadIdx.x + o];
        __syncthreads();
    }
    if (threadIdx.x == 0) out[0] = s[0] / (float)NROWS;
}

// ---------------- launch ----------------
extern "C" void kernel_launch(void* const* d_in, const int* in_sizes, int n_in,
                              void* d_out, int out_size) {
    const float* x   = (const float*)d_in[0];
    const int*   tgt = (const int*)d_in[1];
    float* out = (float*)d_out;

    cudaFuncSetAttribute(gemm_loss_kernel, cudaFuncAttributeMaxDynamicSharedMemorySize, SMEM_TOTAL);

    convert_kernel<<<4096, 256>>>(x, tgt);
    gemm_loss_kernel<<<NBLOCKS, NTHREADS, SMEM_TOTAL>>>();
    reduce_kernel<<<1, 256>>>(out);
}

// round 17
// speedup vs baseline: 1.8198x; 1.0208x over previous
#include <cuda_runtime.h>
#include <cuda_fp16.h>
#include <cstdint>

// ---------------- problem constants ----------------
static constexpr int NROWS   = 8192;
static constexpr int DDIM    = 1024;
static constexpr float MARGIN = 0.3f;

// CTA tile: 128 (M, A-rows) x 256 (N, B-rows)
static constexpr int BM = 128;
static constexpr int BN = 256;
// triangular cover: row-tile bi (of 64) needs col-tiles 0..bi/2 -> 1056 blocks
static constexpr int NBLOCKS = 1056;

static constexpr int STAGES      = 3;
static constexpr int BK          = 64;                 // fp16 elems per K stage (128 B/row)
static constexpr int NKCHUNKS    = DDIM / BK;          // 16
static constexpr int A_BYTES     = BM * 128;           // 16 KB
static constexpr int B_BYTES     = BN * 128;           // 32 KB
static constexpr int STAGE_BYTES = A_BYTES + B_BYTES;  // 48 KB
static constexpr int SMEM_TOTAL  = STAGES * STAGE_BYTES; // 144 KB dynamic

static constexpr int NTHREADS = 512;                   // 16 warps -> 4 per SMSP

// ---------------- scratch (no allocs allowed) ----------------
__device__ __half g_xh[(size_t)NROWS * DDIM];   // 16MB fp16 copy of X
__device__ int   g_tgt[NROWS];
__device__ float g_partials[NBLOCKS];
__device__ unsigned int g_ticket;

// ---------------- helpers ----------------
__device__ __forceinline__ uint32_t smem_to_u32(const void* p) {
    uint32_t a;
    asm("{ .reg .u64 t; cvta.to.shared.u64 t, %1; cvt.u32.u64 %0, t; }" : "=r"(a) : "l"(p));
    return a;
}
#define SW128(off) ((off) ^ (((off) >> 3) & 0x70))

__device__ __forceinline__ void cp_async16(uint32_t smem_dst, const void* gptr) {
    asm volatile("cp.async.cg.shared.global [%0], [%1], 16;"
        :: "r"(smem_dst), "l"(__cvta_generic_to_global(gptr)) : "memory");
}
__device__ __forceinline__ void cp_commit() {
    asm volatile("cp.async.commit_group;" ::: "memory");
}
template <int N> __device__ __forceinline__ void cp_wait() {
    asm volatile("cp.async.wait_group %0;" :: "n"(N) : "memory");
}

__device__ __forceinline__ void ldmatrix_x4(uint32_t& r0, uint32_t& r1, uint32_t& r2, uint32_t& r3,
                                            uint32_t addr) {
    asm volatile("ldmatrix.sync.aligned.m8n8.x4.shared.b16 {%0,%1,%2,%3}, [%4];"
        : "=r"(r0), "=r"(r1), "=r"(r2), "=r"(r3) : "r"(addr));
}

// fp16 in, fp16 accumulate: D fragment = 2 x f16x2 regs
__device__ __forceinline__ void mma_16816_f16(uint32_t* c, const uint32_t* a, uint32_t b0, uint32_t b1) {
    asm volatile("mma.sync.aligned.m16n8k16.row.col.f16.f16.f16.f16 "
        "{%0,%1}, {%2,%3,%4,%5}, {%6,%7}, {%0,%1};"
        : "+r"(c[0]), "+r"(c[1])
        : "r"(a[0]), "r"(a[1]), "r"(a[2]), "r"(a[3]), "r"(b0), "r"(b1));
}

// ---------------- kernel 1: fp32 -> fp16 + targets + ticket reset ----------------
__global__ void convert_kernel(const float* __restrict__ x, const int* __restrict__ tgt) {
    int tid = blockIdx.x * blockDim.x + threadIdx.x;
    int nthreads = gridDim.x * blockDim.x;
    if (tid == 0) g_ticket = 0u;            // reset per launch (graph replay safe)
    const float4* x4 = (const float4*)x;
    uint2* out = (uint2*)g_xh;
    const int n4 = NROWS * DDIM / 4;
    for (int i = tid; i < n4; i += nthreads) {
        float4 v = x4[i];
        __half2 lo = __float22half2_rn(make_float2(v.x, v.y));
        __half2 hi = __float22half2_rn(make_float2(v.z, v.w));
        uint2 o;
        o.x = *(uint32_t*)&lo;
        o.y = *(uint32_t*)&hi;
        out[i] = o;
    }
    if (tid < NROWS) g_tgt[tid] = tgt[tid];
}

// ---------------- kernel 2: 128x256-tile fp16 GEMM + fused epilogue + final reduce ----
__global__ void __launch_bounds__(NTHREADS, 1)
gemm_loss_kernel(float* __restrict__ out) {
    extern __shared__ char smem[];
    __shared__ int   s_tgtA[BM];
    __shared__ int   s_tgtB[BN];
    __shared__ float s_red[16];
    __shared__ int   s_last;

    const uint32_t smem_base = smem_to_u32(smem);
    const int tid = threadIdx.x;
    const int wid = tid >> 5;
    const int lid = tid & 31;

    // block -> (bi, bjc): row-tile bi has (bi/2 + 1) col-tiles
    int k = blockIdx.x;
    int bi = 0;
    for (;;) {
        int nb = (bi >> 1) + 1;
        if (k < nb) break;
        k -= nb;
        bi++;
    }
    const int bjc = k;
    const int row0 = bi * BM;
    const int col0 = bjc * BN;

    if (tid < BM) s_tgtA[tid] = g_tgt[row0 + tid];
    if (tid < BN) s_tgtB[tid] = g_tgt[col0 + tid];

    // warp layout: 2 warps along M (64 rows), 8 along N (32 cols); warp tile 64x32
    const int warp_m = (wid & 1) * 64;
    const int warp_n = (wid >> 1) * 32;

    // ---- cp.async fill assignments (512 threads) ----
    const int arow = tid >> 2;
    const int aq   = (tid & 3) * 32;
    const int brow = tid >> 1;
    const int bh   = (tid & 1) * 64;
    const char* gArow = (const char*)g_xh + ((size_t)(row0 + arow)) * (DDIM * 2) + aq;
    const char* gBrow = (const char*)g_xh + ((size_t)(col0 + brow)) * (DDIM * 2) + bh;

    auto fill = [&](int kc, int buf) {
        uint32_t sA = smem_base + buf * STAGE_BYTES;
        uint32_t sB = sA + A_BYTES;
        const char* ga = gArow + kc * 128;
        const char* gb = gBrow + kc * 128;
        #pragma unroll
        for (int j = 0; j < 2; j++) {
            uint32_t off = SW128((uint32_t)(arow * 128 + aq + j * 16));
            cp_async16(sA + off, ga + j * 16);
        }
        #pragma unroll
        for (int j = 0; j < 4; j++) {
            uint32_t off = SW128((uint32_t)(brow * 128 + bh + j * 16));
            cp_async16(sB + off, gb + j * 16);
        }
    };

    // ---- accumulators: warp tile 64x32 = 4 (m16) x 4 (n8) f16x2-pair fragments ----
    uint32_t c[4][4][2];
    #pragma unroll
    for (int mi = 0; mi < 4; mi++)
        #pragma unroll
        for (int ni = 0; ni < 4; ni++) {
            c[mi][ni][0] = 0u;
            c[mi][ni][1] = 0u;
        }

    const int lrow  = lid & 15;
    const int lkoff = (lid >> 4) * 16;

    // prologue
    #pragma unroll
    for (int s = 0; s < STAGES - 1; s++) { fill(s, s); cp_commit(); }

    for (int kc = 0; kc < NKCHUNKS; kc++) {
        const int buf = kc % STAGES;
        cp_wait<STAGES - 2>();
        __syncthreads();

        const int kf = kc + STAGES - 1;
        if (kf < NKCHUNKS) fill(kf, kf % STAGES);
        cp_commit();

        const uint32_t sA = smem_base + buf * STAGE_BYTES;
        const uint32_t sB = sA + A_BYTES;

        #pragma unroll
        for (int ks = 0; ks < BK / 16; ks++) {
            const int kbyte = ks * 32 + lkoff;
            uint32_t a[4][4];
            #pragma unroll
            for (int mi = 0; mi < 4; mi++) {
                uint32_t off = SW128((uint32_t)((warp_m + mi * 16 + lrow) * 128 + kbyte));
                ldmatrix_x4(a[mi][0], a[mi][1], a[mi][2], a[mi][3], sA + off);
            }
            uint32_t b[2][4];
            #pragma unroll
            for (int ng = 0; ng < 2; ng++) {
                uint32_t off = SW128((uint32_t)((warp_n + ng * 16 + lrow) * 128 + kbyte));
                ldmatrix_x4(b[ng][0], b[ng][1], b[ng][2], b[ng][3], sB + off);
            }
            #pragma unroll
            for (int mi = 0; mi < 4; mi++)
                #pragma unroll
                for (int ni = 0; ni < 4; ni++) {
                    const int ng = ni >> 1, s2 = ni & 1;
                    mma_16816_f16(c[mi][ni], a[mi], b[ng][s2], b[ng][2 + s2]);
                }
        }
    }
    __syncthreads();

    // ---- fused epilogue: unpack f16x2 + masked hinge sums, strict lower triangle (w=2) ----
    float acc = 0.0f;
    #pragma unroll
    for (int mi = 0; mi < 4; mi++) {
        const int lr0 = warp_m + mi * 16 + (lid >> 2);
        const int gr0 = row0 + lr0;
        const int gr1 = gr0 + 8;
        const int tr0 = s_tgtA[lr0];
        const int tr1 = s_tgtA[lr0 + 8];
        #pragma unroll
        for (int ni = 0; ni < 4; ni++) {
            const int lc0 = warp_n + ni * 8 + 2 * (lid & 3);
            const int gc0 = col0 + lc0;
            const int gc1 = gc0 + 1;
            const int tc0 = s_tgtB[lc0];
            const int tc1 = s_tgtB[lc0 + 1];
            float2 lo = __half22float2(*(const __half2*)&c[mi][ni][0]);
            float2 hi = __half22float2(*(const __half2*)&c[mi][ni][1]);
            const float f0 = lo.x, f1 = lo.y, f2 = hi.x, f3 = hi.y;
            if (gc0 < gr0) {
                if (tr0 == tc0) { if (f0 < 1.0f) acc += 1.0f - f0; } else if (f0 > MARGIN) acc += f0;
            }
            if (gc1 < gr0) {
                if (tr0 == tc1) { if (f1 < 1.0f) acc += 1.0f - f1; } else if (f1 > MARGIN) acc += f1;
            }
            if (gc0 < gr1) {
                if (tr1 == tc0) { if (f2 < 1.0f) acc += 1.0f - f2; } else if (f2 > MARGIN) acc += f2;
            }
            if (gc1 < gr1) {
                if (tr1 == tc1) { if (f3 < 1.0f) acc += 1.0f - f3; } else if (f3 > MARGIN) acc += f3;
            }
        }
    }
    #pragma unroll
    for (int o = 16; o; o >>= 1) acc += __shfl_xor_sync(0xFFFFFFFFu, acc, o);
    if (lid == 0) s_red[wid] = acc;
    __syncthreads();
    if (tid == 0) {
        float tot = 0.0f;
        #pragma unroll
        for (int w = 0; w < 16; w++) tot += s_red[w];
        g_partials[blockIdx.x] = 2.0f * tot;
        __threadfence();                             // publish partial before taking ticket
        unsigned int t = atomicAdd(&g_ticket, 1u);
        s_last = (t == (unsigned int)(NBLOCKS - 1)) ? 1 : 0;
    }
    __syncthreads();

    // ---- last block (by ticket) does the deterministic final reduction ----
    if (s_last) {
        __threadfence();                             // order: all partials visible
        float v = 0.0f;
        for (int i = tid; i < NBLOCKS; i += NTHREADS) v += __ldcg(&g_partials[i]);
        #pragma unroll
        for (int o = 16; o; o >>= 1) v += __shfl_xor_sync(0xFFFFFFFFu, v, o);
        if (lid == 0) s_red[wid] = v;
        __syncthreads();
        if (tid == 0) {
            float tot = 0.0f;
            #pragma unroll
            for (int w = 0; w < 16; w++) tot += s_red[w];
            out[0] = tot / (float)NROWS;
        }
    }
}

// ---------------- launch ----------------
extern "C" void kernel_launch(void* const* d_in, const int* in_sizes, int n_in,
                              void* d_out, int out_size) {
    const float* x   = (const float*)d_in[0];
    const int*   tgt = (const int*)d_in[1];
    float* out = (float*)d_out;

    cudaFuncSetAttribute(gemm_loss_kernel, cudaFuncAttributeMaxDynamicSharedMemorySize, SMEM_TOTAL);

    convert_kernel<<<8192, 256>>>(x, tgt);
    gemm_loss_kernel<<<NBLOCKS, NTHREADS, SMEM_TOTAL>>>(out);
}